// round 2
// baseline (speedup 1.0000x reference)
#include <cuda_runtime.h>
#include <math.h>

#define HID 2048
#define TT 1024
#define NH 32
#define HD 64
#define INTER 5632

// ---------------- scratch (no allocations allowed) ----------------
__device__ float g_h[TT*HID];
__device__ float g_qr[TT*HID];
__device__ float g_kr[TT*HID];
__device__ float g_vr[TT*HID];
__device__ float g_q[TT*HID];
__device__ float g_k[TT*HID];
__device__ float g_v[TT*HID];
__device__ float g_beta[TT*NH];
__device__ float g_o[TT*HID];
__device__ float g_on[TT*HID];
__device__ float g_x1[TT*HID];
__device__ float g_h2[TT*HID];
__device__ float g_gate[TT*INTER];
__device__ float g_up[TT*INTER];
__device__ float g_act[TT*INTER];
__device__ float g_Ssc[NH*HD*HD];

// ---------------- RMSNorm: one block per row ----------------
__global__ void rmsnorm_k(const float* __restrict__ x, const float* __restrict__ w,
                          float* __restrict__ out) {
    int row = blockIdx.x;
    const float* xr = x + row * HID;
    float ss = 0.f;
    for (int i = threadIdx.x; i < HID; i += 256) { float v = xr[i]; ss += v * v; }
    #pragma unroll
    for (int m = 16; m; m >>= 1) ss += __shfl_xor_sync(0xffffffffu, ss, m);
    __shared__ float red[8];
    if ((threadIdx.x & 31) == 0) red[threadIdx.x >> 5] = ss;
    __syncthreads();
    if (threadIdx.x < 8) {
        float r = red[threadIdx.x];
        #pragma unroll
        for (int m = 4; m; m >>= 1) r += __shfl_xor_sync(0xffu, r, m);
        if (threadIdx.x == 0) red[0] = r;
    }
    __syncthreads();
    float scale = rsqrtf(red[0] * (1.0f / (float)HID) + 1e-6f);
    for (int i = threadIdx.x; i < HID; i += 256)
        out[row * HID + i] = xr[i] * scale * w[i];
}

// ---------------- SGEMM: C[M,N] = A[M,K] * B[N,K]^T (+ residual) ----------------
// 128x128x16 tile, 256 threads, 8x8 per-thread. M,N multiples of 128, K of 16.
template <int RES>
__global__ void __launch_bounds__(256, 2)
sgemm_nt(const float* __restrict__ A, const float* __restrict__ B,
         const float* __restrict__ Rsd, float* __restrict__ C,
         int M, int N, int K) {
    __shared__ float As[16][128];
    __shared__ float Bs[16][128];
    int tid = threadIdx.x;
    int row0 = blockIdx.y * 128, col0 = blockIdx.x * 128;
    int lr = tid >> 2;            // 0..63
    int lc = (tid & 3) << 2;      // 0,4,8,12
    const float* Ap = A + (row0 + lr) * K + lc;
    const float* Bp = B + (col0 + lr) * K + lc;
    int ty = tid >> 4, tx = tid & 15;

    float acc[8][8];
    #pragma unroll
    for (int i = 0; i < 8; i++)
        #pragma unroll
        for (int j = 0; j < 8; j++) acc[i][j] = 0.f;

    for (int k0 = 0; k0 < K; k0 += 16) {
        float4 a0 = *(const float4*)(Ap);
        float4 a1 = *(const float4*)(Ap + 64 * K);
        float4 b0 = *(const float4*)(Bp);
        float4 b1 = *(const float4*)(Bp + 64 * K);
        As[lc + 0][lr] = a0.x; As[lc + 1][lr] = a0.y; As[lc + 2][lr] = a0.z; As[lc + 3][lr] = a0.w;
        As[lc + 0][lr + 64] = a1.x; As[lc + 1][lr + 64] = a1.y; As[lc + 2][lr + 64] = a1.z; As[lc + 3][lr + 64] = a1.w;
        Bs[lc + 0][lr] = b0.x; Bs[lc + 1][lr] = b0.y; Bs[lc + 2][lr] = b0.z; Bs[lc + 3][lr] = b0.w;
        Bs[lc + 0][lr + 64] = b1.x; Bs[lc + 1][lr + 64] = b1.y; Bs[lc + 2][lr + 64] = b1.z; Bs[lc + 3][lr + 64] = b1.w;
        __syncthreads();
        #pragma unroll
        for (int kk = 0; kk < 16; kk++) {
            float ra[8], rb[8];
            *(float4*)(ra)     = *(const float4*)&As[kk][ty * 8];
            *(float4*)(ra + 4) = *(const float4*)&As[kk][ty * 8 + 4];
            *(float4*)(rb)     = *(const float4*)&Bs[kk][tx * 8];
            *(float4*)(rb + 4) = *(const float4*)&Bs[kk][tx * 8 + 4];
            #pragma unroll
            for (int i = 0; i < 8; i++)
                #pragma unroll
                for (int j = 0; j < 8; j++) acc[i][j] = fmaf(ra[i], rb[j], acc[i][j]);
        }
        __syncthreads();
        Ap += 16; Bp += 16;
    }

    #pragma unroll
    for (int i = 0; i < 8; i++) {
        int crow = row0 + ty * 8 + i;
        float* cp = C + crow * N + col0 + tx * 8;
        float4 v0 = make_float4(acc[i][0], acc[i][1], acc[i][2], acc[i][3]);
        float4 v1 = make_float4(acc[i][4], acc[i][5], acc[i][6], acc[i][7]);
        if (RES) {
            const float* rp = Rsd + crow * N + col0 + tx * 8;
            float4 r0 = *(const float4*)(rp);
            float4 r1 = *(const float4*)(rp + 4);
            v0.x += r0.x; v0.y += r0.y; v0.z += r0.z; v0.w += r0.w;
            v1.x += r1.x; v1.y += r1.y; v1.z += r1.z; v1.w += r1.w;
        }
        *(float4*)(cp) = v0;
        *(float4*)(cp + 4) = v1;
    }
}

// ---------------- causal depthwise conv (K=4) + silu(silu(.)) ----------------
__global__ void conv_silu2_k(const float* __restrict__ in, const float* __restrict__ w,
                             float* __restrict__ out) {
    int idx = blockIdx.x * blockDim.x + threadIdx.x;
    if (idx >= TT * HID) return;
    int c = idx & (HID - 1);
    int t = idx >> 11;
    const float* wc = w + c * 4;
    float acc = 0.f;
    #pragma unroll
    for (int j = 0; j < 4; j++) {
        int ti = t - 3 + j;
        if (ti >= 0) acc = fmaf(in[ti * HID + c], wc[j], acc);
    }
    float s1 = acc / (1.f + expf(-acc));
    float s2 = s1 / (1.f + expf(-s1));
    out[idx] = s2;
}

// ---------------- per-head L2 norm (in-place), one warp per (t, head) ----------------
__global__ void l2norm_k(float* __restrict__ p) {
    int t = blockIdx.x;
    int h = threadIdx.x >> 5, l = threadIdx.x & 31;
    float* r = p + t * HID + h * HD;
    float a = r[l], b = r[l + 32];
    float ss = a * a + b * b;
    #pragma unroll
    for (int m = 16; m; m >>= 1) ss += __shfl_xor_sync(0xffffffffu, ss, m);
    float inv = 1.f / fmaxf(sqrtf(ss), 1e-12f);
    r[l] = a * inv;
    r[l + 32] = b * inv;
}

// ---------------- beta = sigmoid(h @ Wbeta^T), one warp per (t, head) ----------------
__global__ void beta_k(const float* __restrict__ hbuf, const float* __restrict__ Wb,
                       float* __restrict__ beta) {
    int t = blockIdx.x;
    int hh = threadIdx.x >> 5, l = threadIdx.x & 31;
    const float* hr = hbuf + t * HID;
    const float* wr = Wb + hh * HID;
    float s = 0.f;
    for (int i = l; i < HID; i += 32) s = fmaf(hr[i], wr[i], s);
    #pragma unroll
    for (int m = 16; m; m >>= 1) s += __shfl_xor_sync(0xffffffffu, s, m);
    if (l == 0) beta[t * NH + hh] = 1.f / (1.f + expf(-s));
}

// ---------------- delta scan ----------------
// Each (head, state-row v) evolves independently: 2048 tasks x 4 lanes, 16 state
// floats/lane in registers. Fused output: o = S_old.q - beta*err*(k.q).
__global__ void delta_scan_k(const float* __restrict__ kb, const float* __restrict__ qb,
                             const float* __restrict__ vb, const float* __restrict__ betab,
                             float* __restrict__ ob, float* __restrict__ Sout) {
    int gtid = blockIdx.x * blockDim.x + threadIdx.x;
    int sub  = gtid & 3;
    int task = gtid >> 2;          // 0..2047
    int head = task >> 6;
    int row  = task & 63;
    int c0   = sub << 4;

    float S[16];
    #pragma unroll
    for (int j = 0; j < 16; j++) S[j] = 0.f;

    const float* kp = kb + head * HD + c0;
    const float* qp = qb + head * HD + c0;
    const float* vp = vb + head * HD + row;
    const float* bp = betab + head;
    float* op = ob + head * HD + row;

    for (int t = 0; t < TT; t++) {
        float kk[16], qq[16];
        *(float4*)(kk)      = *(const float4*)(kp);
        *(float4*)(kk + 4)  = *(const float4*)(kp + 4);
        *(float4*)(kk + 8)  = *(const float4*)(kp + 8);
        *(float4*)(kk + 12) = *(const float4*)(kp + 12);
        *(float4*)(qq)      = *(const float4*)(qp);
        *(float4*)(qq + 4)  = *(const float4*)(qp + 4);
        *(float4*)(qq + 8)  = *(const float4*)(qp + 8);
        *(float4*)(qq + 12) = *(const float4*)(qp + 12);
        float vt = *vp;
        float bt = *bp;

        float a = 0.f, b = 0.f, c = 0.f;
        #pragma unroll
        for (int j = 0; j < 16; j++) {
            a = fmaf(S[j], kk[j], a);
            b = fmaf(S[j], qq[j], b);
            c = fmaf(kk[j], qq[j], c);
        }
        a += __shfl_xor_sync(0xffffffffu, a, 1);
        b += __shfl_xor_sync(0xffffffffu, b, 1);
        c += __shfl_xor_sync(0xffffffffu, c, 1);
        a += __shfl_xor_sync(0xffffffffu, a, 2);
        b += __shfl_xor_sync(0xffffffffu, b, 2);
        c += __shfl_xor_sync(0xffffffffu, c, 2);

        float coef = bt * (a - vt);
        float ot = b - coef * c;
        #pragma unroll
        for (int j = 0; j < 16; j++) S[j] = fmaf(-coef, kk[j], S[j]);
        if (sub == 0) op[t * HID] = ot;

        kp += HID; qp += HID; vp += HID; bp += NH;
    }

    #pragma unroll
    for (int j = 0; j < 16; j++)
        Sout[head * HD * HD + row * HD + c0 + j] = S[j];
}

// ---------------- SwiGLU elementwise ----------------
__global__ void swiglu_k(const float* __restrict__ g, const float* __restrict__ u,
                         float* __restrict__ out, int n) {
    int i = blockIdx.x * blockDim.x + threadIdx.x;
    if (i < n) {
        float x = g[i];
        out[i] = (x / (1.f + expf(-x))) * u[i];
    }
}

// ---------------- launch ----------------
extern "C" void kernel_launch(void* const* d_in, const int* in_sizes, int n_in,
                              void* d_out, int out_size) {
    const float* x_in   = (const float*)d_in[0];
    const float* attn_w = (const float*)d_in[1];
    const float* Wq     = (const float*)d_in[2];
    const float* Wk     = (const float*)d_in[3];
    const float* Wv     = (const float*)d_in[4];
    const float* cq     = (const float*)d_in[5];
    const float* ck     = (const float*)d_in[6];
    const float* cv     = (const float*)d_in[7];
    const float* Wb     = (const float*)d_in[8];
    const float* out_w  = (const float*)d_in[9];
    const float* Wout   = (const float*)d_in[10];
    const float* mlp_w  = (const float*)d_in[11];
    const float* Wg     = (const float*)d_in[12];
    const float* Wu     = (const float*)d_in[13];
    const float* Wd     = (const float*)d_in[14];

    float *h, *qr, *kr, *vr, *q, *k, *v, *beta, *o, *on, *x1, *h2, *gate, *up, *act, *Ssc;
    cudaGetSymbolAddress((void**)&h,   g_h);
    cudaGetSymbolAddress((void**)&qr,  g_qr);
    cudaGetSymbolAddress((void**)&kr,  g_kr);
    cudaGetSymbolAddress((void**)&vr,  g_vr);
    cudaGetSymbolAddress((void**)&q,   g_q);
    cudaGetSymbolAddress((void**)&k,   g_k);
    cudaGetSymbolAddress((void**)&v,   g_v);
    cudaGetSymbolAddress((void**)&beta,g_beta);
    cudaGetSymbolAddress((void**)&o,   g_o);
    cudaGetSymbolAddress((void**)&on,  g_on);
    cudaGetSymbolAddress((void**)&x1,  g_x1);
    cudaGetSymbolAddress((void**)&h2,  g_h2);
    cudaGetSymbolAddress((void**)&gate,g_gate);
    cudaGetSymbolAddress((void**)&up,  g_up);
    cudaGetSymbolAddress((void**)&act, g_act);
    cudaGetSymbolAddress((void**)&Ssc, g_Ssc);

    float* out_x = (float*)d_out;
    float* Sdst = (out_size >= TT * HID + NH * HD * HD) ? (out_x + TT * HID) : Ssc;

    // ---- attention sub-block ----
    rmsnorm_k<<<TT, 256>>>(x_in, attn_w, h);

    dim3 g2(HID / 128, TT / 128);     // (16, 8)
    sgemm_nt<0><<<g2, 256>>>(h, Wq, nullptr, qr, TT, HID, HID);
    sgemm_nt<0><<<g2, 256>>>(h, Wk, nullptr, kr, TT, HID, HID);
    sgemm_nt<0><<<g2, 256>>>(h, Wv, nullptr, vr, TT, HID, HID);

    int nTH = TT * HID;
    conv_silu2_k<<<nTH / 256, 256>>>(qr, cq, q);
    conv_silu2_k<<<nTH / 256, 256>>>(kr, ck, k);
    conv_silu2_k<<<nTH / 256, 256>>>(vr, cv, v);

    l2norm_k<<<TT, 1024>>>(q);
    l2norm_k<<<TT, 1024>>>(k);
    beta_k<<<TT, 1024>>>(h, Wb, beta);

    delta_scan_k<<<64, 128>>>(k, q, v, beta, o, Sdst);

    rmsnorm_k<<<TT, 256>>>(o, out_w, on);
    sgemm_nt<1><<<g2, 256>>>(on, Wout, x_in, x1, TT, HID, HID);

    // ---- MLP sub-block ----
    rmsnorm_k<<<TT, 256>>>(x1, mlp_w, h2);
    dim3 g3(INTER / 128, TT / 128);   // (44, 8)
    sgemm_nt<0><<<g3, 256>>>(h2, Wg, nullptr, gate, TT, INTER, HID);
    sgemm_nt<0><<<g3, 256>>>(h2, Wu, nullptr, up, TT, INTER, HID);
    swiglu_k<<<(TT * INTER) / 256, 256>>>(gate, up, act, TT * INTER);
    sgemm_nt<1><<<g2, 256>>>(act, Wd, x1, out_x, TT, HID, INTER);
}

// round 4
// speedup vs baseline: 2.2744x; 2.2744x over previous
#include <cuda_runtime.h>
#include <cuda_bf16.h>
#include <math.h>
#include <stdint.h>

#define HID 2048
#define TT 1024
#define NH 32
#define HD 64
#define INTER 5632

// ---------------- scratch (no allocations allowed) ----------------
__device__ float g_h[TT*HID];
__device__ float g_qr[TT*HID];
__device__ float g_kr[TT*HID];
__device__ float g_vr[TT*HID];
__device__ float g_q[TT*HID];
__device__ float g_k[TT*HID];
__device__ float g_v[TT*HID];
__device__ float g_beta[TT*NH];
__device__ float g_o[TT*HID];
__device__ float g_on[TT*HID];
__device__ float g_x1[TT*HID];
__device__ float g_h2[TT*HID];
__device__ float g_gate[TT*INTER];
__device__ float g_up[TT*INTER];
__device__ float g_act[TT*INTER];
__device__ float g_Ssc[NH*HD*HD];

// ================= warp-mma helpers (family-agnostic, compile at compute_103) =================
__device__ __forceinline__ uint32_t smem_u32(const void* p) {
    uint32_t a;
    asm("{ .reg .u64 t; cvta.to.shared.u64 t, %1; cvt.u32.u64 %0, t; }" : "=r"(a) : "l"(p));
    return a;
}

__device__ __forceinline__ void ldmx4(uint32_t& r0, uint32_t& r1, uint32_t& r2, uint32_t& r3,
                                      uint32_t addr) {
    asm volatile("ldmatrix.sync.aligned.m8n8.x4.shared.b16 {%0,%1,%2,%3}, [%4];"
                 : "=r"(r0), "=r"(r1), "=r"(r2), "=r"(r3) : "r"(addr));
}

__device__ __forceinline__ void mma16816(float* c, const uint32_t* a, const uint32_t* b) {
    asm volatile(
        "mma.sync.aligned.m16n8k16.row.col.f32.bf16.bf16.f32 "
        "{%0,%1,%2,%3}, {%4,%5,%6,%7}, {%8,%9}, {%0,%1,%2,%3};"
        : "+f"(c[0]), "+f"(c[1]), "+f"(c[2]), "+f"(c[3])
        : "r"(a[0]), "r"(a[1]), "r"(a[2]), "r"(a[3]), "r"(b[0]), "r"(b[1]));
}

__device__ __forceinline__ uint32_t pack_bf16x2(float a, float b) {
    __nv_bfloat162 r;
    r.x = __float2bfloat16_rn(a);
    r.y = __float2bfloat16_rn(b);
    return *(uint32_t*)&r;
}

// split v into h (bf16) and l (bf16 of remainder); store 4 elems as uint2
__device__ __forceinline__ void split_store4(float4 v, __nv_bfloat16* hp, __nv_bfloat16* lp) {
    float h0 = __bfloat162float(__float2bfloat16_rn(v.x));
    float h1 = __bfloat162float(__float2bfloat16_rn(v.y));
    float h2 = __bfloat162float(__float2bfloat16_rn(v.z));
    float h3 = __bfloat162float(__float2bfloat16_rn(v.w));
    *(uint2*)hp = make_uint2(pack_bf16x2(h0, h1), pack_bf16x2(h2, h3));
    *(uint2*)lp = make_uint2(pack_bf16x2(v.x - h0, v.y - h1), pack_bf16x2(v.z - h2, v.w - h3));
}

// ================= tensor-core GEMM: C[M,N] = A[M,K] @ B[N,K]^T (+Rsd) =================
// bf16-split 3-product accumulation (~1e-5 accuracy). 128x128 CTA tile, BK=32,
// 8 warps (2x4), 64x32 warp tiles, register-prefetch of next K chunk.
#define PADW 40   // bf16 elements per smem row (80B stride -> conflict-free ldmatrix)

template <int RES>
__global__ void __launch_bounds__(256, 1)
mgemm(const float* __restrict__ A, const float* __restrict__ B,
      const float* __restrict__ Rsd, float* __restrict__ C,
      int M, int N, int K) {
    __shared__ __nv_bfloat16 sAh[128][PADW];
    __shared__ __nv_bfloat16 sAl[128][PADW];
    __shared__ __nv_bfloat16 sBh[128][PADW];
    __shared__ __nv_bfloat16 sBl[128][PADW];

    const int tid = threadIdx.x;
    const int lane = tid & 31;
    const int wid = tid >> 5;
    const int wm = wid & 1;        // 0..1  (M groups of 64)
    const int wn = wid >> 1;       // 0..3  (N groups of 32)
    const int row0 = blockIdx.y * 128, col0 = blockIdx.x * 128;

    const float* Ab = A + (size_t)row0 * K;
    const float* Bb = B + (size_t)col0 * K;

    // per-thread global-load slots: 4 float4 per matrix per chunk
    int rr[4], cc[4];
    #pragma unroll
    for (int i = 0; i < 4; i++) {
        int idx = i * 256 + tid;   // 0..1023
        rr[i] = idx >> 3;          // 0..127
        cc[i] = (idx & 7) * 4;     // 0,4,...,28  (float col within chunk)
    }

    float acc[4][4][4];
    #pragma unroll
    for (int mt = 0; mt < 4; mt++)
        #pragma unroll
        for (int nt = 0; nt < 4; nt++)
            #pragma unroll
            for (int j = 0; j < 4; j++) acc[mt][nt][j] = 0.f;

    // ldmatrix addresses (fixed per thread; column offset varies by kt)
    const uint32_t aH = smem_u32(&sAh[0][0]), aL = smem_u32(&sAl[0][0]);
    const uint32_t bH = smem_u32(&sBh[0][0]), bL = smem_u32(&sBl[0][0]);
    const int aRow = wm * 64 + (lane & 15);          // + mt*16
    const int aCol = (lane >> 4) * 8;                // + kt*16
    const int bRow = wn * 32 + (lane >> 4) * 8 + (lane & 7);   // + nt2*16
    const int bCol = ((lane >> 3) & 1) * 8;          // + kt*16

    const int nchunk = K >> 5;
    float4 pa[4], pb[4];
    #pragma unroll
    for (int i = 0; i < 4; i++) {
        pa[i] = *(const float4*)(Ab + (size_t)rr[i] * K + cc[i]);
        pb[i] = *(const float4*)(Bb + (size_t)rr[i] * K + cc[i]);
    }

    for (int c = 0; c < nchunk; c++) {
        // store current chunk (split h/l) into smem
        #pragma unroll
        for (int i = 0; i < 4; i++) {
            split_store4(pa[i], &sAh[rr[i]][cc[i]], &sAl[rr[i]][cc[i]]);
            split_store4(pb[i], &sBh[rr[i]][cc[i]], &sBl[rr[i]][cc[i]]);
        }
        __syncthreads();

        // prefetch next chunk while computing
        if (c + 1 < nchunk) {
            const float* An = Ab + (c + 1) * 32;
            const float* Bn = Bb + (c + 1) * 32;
            #pragma unroll
            for (int i = 0; i < 4; i++) {
                pa[i] = *(const float4*)(An + (size_t)rr[i] * K + cc[i]);
                pb[i] = *(const float4*)(Bn + (size_t)rr[i] * K + cc[i]);
            }
        }

        #pragma unroll
        for (int kt = 0; kt < 2; kt++) {
            uint32_t ah[4][4], al[4][4], bh[4][2], bl[4][2];
            #pragma unroll
            for (int mt = 0; mt < 4; mt++) {
                uint32_t off = ((uint32_t)(aRow + mt * 16) * PADW + aCol + kt * 16) * 2;
                ldmx4(ah[mt][0], ah[mt][1], ah[mt][2], ah[mt][3], aH + off);
                ldmx4(al[mt][0], al[mt][1], al[mt][2], al[mt][3], aL + off);
            }
            #pragma unroll
            for (int n2 = 0; n2 < 2; n2++) {
                uint32_t off = ((uint32_t)(bRow + n2 * 16) * PADW + bCol + kt * 16) * 2;
                uint32_t r0, r1, r2, r3;
                ldmx4(r0, r1, r2, r3, bH + off);
                bh[n2 * 2][0] = r0; bh[n2 * 2][1] = r1;
                bh[n2 * 2 + 1][0] = r2; bh[n2 * 2 + 1][1] = r3;
                ldmx4(r0, r1, r2, r3, bL + off);
                bl[n2 * 2][0] = r0; bl[n2 * 2][1] = r1;
                bl[n2 * 2 + 1][0] = r2; bl[n2 * 2 + 1][1] = r3;
            }
            #pragma unroll
            for (int mt = 0; mt < 4; mt++)
                #pragma unroll
                for (int nt = 0; nt < 4; nt++) {
                    mma16816(acc[mt][nt], ah[mt], bh[nt]);
                    mma16816(acc[mt][nt], ah[mt], bl[nt]);
                    mma16816(acc[mt][nt], al[mt], bh[nt]);
                }
        }
        __syncthreads();
    }

    // epilogue: c0,c1 -> (row, col..col+1); c2,c3 -> (row+8, col..col+1)
    #pragma unroll
    for (int mt = 0; mt < 4; mt++) {
        int r0g = row0 + wm * 64 + mt * 16 + (lane >> 2);
        #pragma unroll
        for (int nt = 0; nt < 4; nt++) {
            int cg = col0 + wn * 32 + nt * 8 + (lane & 3) * 2;
            float2 v0 = make_float2(acc[mt][nt][0], acc[mt][nt][1]);
            float2 v1 = make_float2(acc[mt][nt][2], acc[mt][nt][3]);
            if (RES) {
                float2 q0 = *(const float2*)(Rsd + (size_t)r0g * N + cg);
                float2 q1 = *(const float2*)(Rsd + (size_t)(r0g + 8) * N + cg);
                v0.x += q0.x; v0.y += q0.y;
                v1.x += q1.x; v1.y += q1.y;
            }
            *(float2*)(C + (size_t)r0g * N + cg) = v0;
            *(float2*)(C + (size_t)(r0g + 8) * N + cg) = v1;
        }
    }
}

// ---------------- RMSNorm: one block per row ----------------
__global__ void rmsnorm_k(const float* __restrict__ x, const float* __restrict__ w,
                          float* __restrict__ out) {
    int row = blockIdx.x;
    const float* xr = x + row * HID;
    float ss = 0.f;
    for (int i = threadIdx.x; i < HID; i += 256) { float v = xr[i]; ss += v * v; }
    #pragma unroll
    for (int m = 16; m; m >>= 1) ss += __shfl_xor_sync(0xffffffffu, ss, m);
    __shared__ float red[8];
    if ((threadIdx.x & 31) == 0) red[threadIdx.x >> 5] = ss;
    __syncthreads();
    if (threadIdx.x < 8) {
        float r = red[threadIdx.x];
        #pragma unroll
        for (int m = 4; m; m >>= 1) r += __shfl_xor_sync(0xffu, r, m);
        if (threadIdx.x == 0) red[0] = r;
    }
    __syncthreads();
    float scale = rsqrtf(red[0] * (1.0f / (float)HID) + 1e-6f);
    for (int i = threadIdx.x; i < HID; i += 256)
        out[row * HID + i] = xr[i] * scale * w[i];
}

// ---------------- causal depthwise conv (K=4) + silu(silu(.)) ----------------
__global__ void conv_silu2_k(const float* __restrict__ in, const float* __restrict__ w,
                             float* __restrict__ out) {
    int idx = blockIdx.x * blockDim.x + threadIdx.x;
    if (idx >= TT * HID) return;
    int c = idx & (HID - 1);
    int t = idx >> 11;
    const float* wc = w + c * 4;
    float acc = 0.f;
    #pragma unroll
    for (int j = 0; j < 4; j++) {
        int ti = t - 3 + j;
        if (ti >= 0) acc = fmaf(in[ti * HID + c], wc[j], acc);
    }
    float s1 = acc / (1.f + expf(-acc));
    float s2 = s1 / (1.f + expf(-s1));
    out[idx] = s2;
}

// ---------------- per-head L2 norm (in-place), one warp per (t, head) ----------------
__global__ void l2norm_k(float* __restrict__ p) {
    int t = blockIdx.x;
    int h = threadIdx.x >> 5, l = threadIdx.x & 31;
    float* r = p + t * HID + h * HD;
    float a = r[l], b = r[l + 32];
    float ss = a * a + b * b;
    #pragma unroll
    for (int m = 16; m; m >>= 1) ss += __shfl_xor_sync(0xffffffffu, ss, m);
    float inv = 1.f / fmaxf(sqrtf(ss), 1e-12f);
    r[l] = a * inv;
    r[l + 32] = b * inv;
}

// ---------------- beta = sigmoid(h @ Wbeta^T), one warp per (t, head) ----------------
__global__ void beta_k(const float* __restrict__ hbuf, const float* __restrict__ Wb,
                       float* __restrict__ beta) {
    int t = blockIdx.x;
    int hh = threadIdx.x >> 5, l = threadIdx.x & 31;
    const float* hr = hbuf + t * HID;
    const float* wr = Wb + hh * HID;
    float s = 0.f;
    for (int i = l; i < HID; i += 32) s = fmaf(hr[i], wr[i], s);
    #pragma unroll
    for (int m = 16; m; m >>= 1) s += __shfl_xor_sync(0xffffffffu, s, m);
    if (l == 0) beta[t * NH + hh] = 1.f / (1.f + expf(-s));
}

// ---------------- delta scan ----------------
__global__ void delta_scan_k(const float* __restrict__ kb, const float* __restrict__ qb,
                             const float* __restrict__ vb, const float* __restrict__ betab,
                             float* __restrict__ ob, float* __restrict__ Sout) {
    int gtid = blockIdx.x * blockDim.x + threadIdx.x;
    int sub  = gtid & 3;
    int task = gtid >> 2;          // 0..2047
    int head = task >> 6;
    int row  = task & 63;
    int c0   = sub << 4;

    float S[16];
    #pragma unroll
    for (int j = 0; j < 16; j++) S[j] = 0.f;

    const float* kp = kb + head * HD + c0;
    const float* qp = qb + head * HD + c0;
    const float* vp = vb + head * HD + row;
    const float* bp = betab + head;
    float* op = ob + head * HD + row;

    for (int t = 0; t < TT; t++) {
        float kk[16], qq[16];
        *(float4*)(kk)      = *(const float4*)(kp);
        *(float4*)(kk + 4)  = *(const float4*)(kp + 4);
        *(float4*)(kk + 8)  = *(const float4*)(kp + 8);
        *(float4*)(kk + 12) = *(const float4*)(kp + 12);
        *(float4*)(qq)      = *(const float4*)(qp);
        *(float4*)(qq + 4)  = *(const float4*)(qp + 4);
        *(float4*)(qq + 8)  = *(const float4*)(qp + 8);
        *(float4*)(qq + 12) = *(const float4*)(qp + 12);
        float vt = *vp;
        float bt = *bp;

        float a = 0.f, b = 0.f, c = 0.f;
        #pragma unroll
        for (int j = 0; j < 16; j++) {
            a = fmaf(S[j], kk[j], a);
            b = fmaf(S[j], qq[j], b);
            c = fmaf(kk[j], qq[j], c);
        }
        a += __shfl_xor_sync(0xffffffffu, a, 1);
        b += __shfl_xor_sync(0xffffffffu, b, 1);
        c += __shfl_xor_sync(0xffffffffu, c, 1);
        a += __shfl_xor_sync(0xffffffffu, a, 2);
        b += __shfl_xor_sync(0xffffffffu, b, 2);
        c += __shfl_xor_sync(0xffffffffu, c, 2);

        float coef = bt * (a - vt);
        float ot = b - coef * c;
        #pragma unroll
        for (int j = 0; j < 16; j++) S[j] = fmaf(-coef, kk[j], S[j]);
        if (sub == 0) op[t * HID] = ot;

        kp += HID; qp += HID; vp += HID; bp += NH;
    }

    #pragma unroll
    for (int j = 0; j < 16; j++)
        Sout[head * HD * HD + row * HD + c0 + j] = S[j];
}

// ---------------- SwiGLU elementwise ----------------
__global__ void swiglu_k(const float* __restrict__ g, const float* __restrict__ u,
                         float* __restrict__ out, int n) {
    int i = blockIdx.x * blockDim.x + threadIdx.x;
    if (i < n) {
        float x = g[i];
        out[i] = (x / (1.f + expf(-x))) * u[i];
    }
}

// ---------------- launch ----------------
extern "C" void kernel_launch(void* const* d_in, const int* in_sizes, int n_in,
                              void* d_out, int out_size) {
    const float* x_in   = (const float*)d_in[0];
    const float* attn_w = (const float*)d_in[1];
    const float* Wq     = (const float*)d_in[2];
    const float* Wk     = (const float*)d_in[3];
    const float* Wv     = (const float*)d_in[4];
    const float* cq     = (const float*)d_in[5];
    const float* ck     = (const float*)d_in[6];
    const float* cv     = (const float*)d_in[7];
    const float* Wb     = (const float*)d_in[8];
    const float* out_w  = (const float*)d_in[9];
    const float* Wout   = (const float*)d_in[10];
    const float* mlp_w  = (const float*)d_in[11];
    const float* Wg     = (const float*)d_in[12];
    const float* Wu     = (const float*)d_in[13];
    const float* Wd     = (const float*)d_in[14];

    float *h, *qr, *kr, *vr, *q, *k, *v, *beta, *o, *on, *x1, *h2, *gate, *up, *act, *Ssc;
    cudaGetSymbolAddress((void**)&h,   g_h);
    cudaGetSymbolAddress((void**)&qr,  g_qr);
    cudaGetSymbolAddress((void**)&kr,  g_kr);
    cudaGetSymbolAddress((void**)&vr,  g_vr);
    cudaGetSymbolAddress((void**)&q,   g_q);
    cudaGetSymbolAddress((void**)&k,   g_k);
    cudaGetSymbolAddress((void**)&v,   g_v);
    cudaGetSymbolAddress((void**)&beta,g_beta);
    cudaGetSymbolAddress((void**)&o,   g_o);
    cudaGetSymbolAddress((void**)&on,  g_on);
    cudaGetSymbolAddress((void**)&x1,  g_x1);
    cudaGetSymbolAddress((void**)&h2,  g_h2);
    cudaGetSymbolAddress((void**)&gate,g_gate);
    cudaGetSymbolAddress((void**)&up,  g_up);
    cudaGetSymbolAddress((void**)&act, g_act);
    cudaGetSymbolAddress((void**)&Ssc, g_Ssc);

    float* out_x = (float*)d_out;
    float* Sdst = (out_size >= TT * HID + NH * HD * HD) ? (out_x + TT * HID) : Ssc;

    // ---- attention sub-block ----
    rmsnorm_k<<<TT, 256>>>(x_in, attn_w, h);

    dim3 g2(HID / 128, TT / 128);     // (16, 8)
    mgemm<0><<<g2, 256>>>(h, Wq, nullptr, qr, TT, HID, HID);
    mgemm<0><<<g2, 256>>>(h, Wk, nullptr, kr, TT, HID, HID);
    mgemm<0><<<g2, 256>>>(h, Wv, nullptr, vr, TT, HID, HID);

    int nTH = TT * HID;
    conv_silu2_k<<<nTH / 256, 256>>>(qr, cq, q);
    conv_silu2_k<<<nTH / 256, 256>>>(kr, ck, k);
    conv_silu2_k<<<nTH / 256, 256>>>(vr, cv, v);

    l2norm_k<<<TT, 1024>>>(q);
    l2norm_k<<<TT, 1024>>>(k);
    beta_k<<<TT, 1024>>>(h, Wb, beta);

    delta_scan_k<<<64, 128>>>(k, q, v, beta, o, Sdst);

    rmsnorm_k<<<TT, 256>>>(o, out_w, on);
    mgemm<1><<<g2, 256>>>(on, Wout, x_in, x1, TT, HID, HID);

    // ---- MLP sub-block ----
    rmsnorm_k<<<TT, 256>>>(x1, mlp_w, h2);
    dim3 g3(INTER / 128, TT / 128);   // (44, 8)
    mgemm<0><<<g3, 256>>>(h2, Wg, nullptr, gate, TT, INTER, HID);
    mgemm<0><<<g3, 256>>>(h2, Wu, nullptr, up, TT, INTER, HID);
    swiglu_k<<<(TT * INTER) / 256, 256>>>(gate, up, act, TT * INTER);
    mgemm<1><<<g2, 256>>>(act, Wd, x1, out_x, TT, HID, INTER);
}

// round 5
// speedup vs baseline: 3.7400x; 1.6444x over previous
#include <cuda_runtime.h>
#include <cuda_bf16.h>
#include <math.h>
#include <stdint.h>

#define HID 2048
#define TT 1024
#define NH 32
#define HD 64
#define INTER 5632

// ---------------- scratch (no allocations allowed) ----------------
__device__ float g_h[TT*HID];
__device__ float g_qr[TT*HID];
__device__ float g_kr[TT*HID];
__device__ float g_vr[TT*HID];
__device__ float g_q[TT*HID];
__device__ float g_k[TT*HID];
__device__ float g_v[TT*HID];
__device__ float g_beta[TT*NH];
__device__ float g_o[TT*HID];
__device__ float g_on[TT*HID];
__device__ float g_x1[TT*HID];
__device__ float g_h2[TT*HID];
__device__ float g_gate[TT*INTER];
__device__ float g_up[TT*INTER];
__device__ float g_act[TT*INTER];
__device__ float g_Ssc[NH*HD*HD];

// ================= warp-mma helpers =================
__device__ __forceinline__ uint32_t smem_u32(const void* p) {
    uint32_t a;
    asm("{ .reg .u64 t; cvta.to.shared.u64 t, %1; cvt.u32.u64 %0, t; }" : "=r"(a) : "l"(p));
    return a;
}

__device__ __forceinline__ void ldmx4(uint32_t& r0, uint32_t& r1, uint32_t& r2, uint32_t& r3,
                                      uint32_t addr) {
    asm volatile("ldmatrix.sync.aligned.m8n8.x4.shared.b16 {%0,%1,%2,%3}, [%4];"
                 : "=r"(r0), "=r"(r1), "=r"(r2), "=r"(r3) : "r"(addr));
}

__device__ __forceinline__ void mma16816(float* c, const uint32_t* a, const uint32_t* b) {
    asm volatile(
        "mma.sync.aligned.m16n8k16.row.col.f32.bf16.bf16.f32 "
        "{%0,%1,%2,%3}, {%4,%5,%6,%7}, {%8,%9}, {%0,%1,%2,%3};"
        : "+f"(c[0]), "+f"(c[1]), "+f"(c[2]), "+f"(c[3])
        : "r"(a[0]), "r"(a[1]), "r"(a[2]), "r"(a[3]), "r"(b[0]), "r"(b[1]));
}

__device__ __forceinline__ uint32_t pack_bf16x2(float a, float b) {
    __nv_bfloat162 r;
    r.x = __float2bfloat16_rn(a);
    r.y = __float2bfloat16_rn(b);
    return *(uint32_t*)&r;
}

__device__ __forceinline__ void split_store4(float4 v, __nv_bfloat16* hp, __nv_bfloat16* lp) {
    float h0 = __bfloat162float(__float2bfloat16_rn(v.x));
    float h1 = __bfloat162float(__float2bfloat16_rn(v.y));
    float h2 = __bfloat162float(__float2bfloat16_rn(v.z));
    float h3 = __bfloat162float(__float2bfloat16_rn(v.w));
    *(uint2*)hp = make_uint2(pack_bf16x2(h0, h1), pack_bf16x2(h2, h3));
    *(uint2*)lp = make_uint2(pack_bf16x2(v.x - h0, v.y - h1), pack_bf16x2(v.z - h2, v.w - h3));
}

// ================= tensor-core GEMM: C[M,N] = A[M,K] @ B[N,K]^T (+Rsd) =================
// bf16-split 3-product accumulation. 128x128 CTA tile, BK=32, 8 warps (2x4),
// double-buffered SMEM (dynamic, 80KB), ONE barrier per K-chunk.
// Batched over blockIdx.z via pointer struct (shared A).
#define PADW 40                // 80B row stride -> conflict-free ldmatrix
#define TSZ  (128 * PADW)      // bf16 elems per tile
#define STAGE_BYTES (4 * TSZ * 2)

struct P3 {
    const float* B[3];
    float* C[3];
    const float* R[3];
};

template <int RES>
__global__ void __launch_bounds__(256, 1)
mgemm(const float* __restrict__ A, P3 p, int M, int N, int K) {
    extern __shared__ __nv_bfloat16 dsm[];
    const float* __restrict__ B = p.B[blockIdx.z];
    float* __restrict__ C = p.C[blockIdx.z];
    const float* __restrict__ Rsd = RES ? p.R[blockIdx.z] : nullptr;

    const int tid = threadIdx.x;
    const int lane = tid & 31;
    const int wid = tid >> 5;
    const int wm = wid & 1;
    const int wn = wid >> 1;
    const int row0 = blockIdx.y * 128, col0 = blockIdx.x * 128;

    const float* Ab = A + (size_t)row0 * K;
    const float* Bb = B + (size_t)col0 * K;

    int rr[4], cc[4];
    #pragma unroll
    for (int i = 0; i < 4; i++) {
        int idx = i * 256 + tid;
        rr[i] = idx >> 3;
        cc[i] = (idx & 7) * 4;
    }

    float acc[4][4][4];
    #pragma unroll
    for (int mt = 0; mt < 4; mt++)
        #pragma unroll
        for (int nt = 0; nt < 4; nt++)
            #pragma unroll
            for (int j = 0; j < 4; j++) acc[mt][nt][j] = 0.f;

    const uint32_t smem_base = smem_u32(dsm);
    const int aRow = wm * 64 + (lane & 15);
    const int aCol = (lane >> 4) * 8;
    const int bRow = wn * 32 + (lane >> 4) * 8 + (lane & 7);
    const int bCol = ((lane >> 3) & 1) * 8;

    const int nchunk = K >> 5;
    float4 pa[4], pb[4];
    #pragma unroll
    for (int i = 0; i < 4; i++) {
        pa[i] = *(const float4*)(Ab + (size_t)rr[i] * K + cc[i]);
        pb[i] = *(const float4*)(Bb + (size_t)rr[i] * K + cc[i]);
    }
    {   // prologue: fill stage 0
        __nv_bfloat16* sAh = dsm;
        __nv_bfloat16* sAl = dsm + TSZ;
        __nv_bfloat16* sBh = dsm + 2 * TSZ;
        __nv_bfloat16* sBl = dsm + 3 * TSZ;
        #pragma unroll
        for (int i = 0; i < 4; i++) {
            split_store4(pa[i], sAh + rr[i] * PADW + cc[i], sAl + rr[i] * PADW + cc[i]);
            split_store4(pb[i], sBh + rr[i] * PADW + cc[i], sBl + rr[i] * PADW + cc[i]);
        }
    }
    __syncthreads();

    for (int c = 0; c < nchunk; c++) {
        const int stage = c & 1;
        const bool more = (c + 1 < nchunk);
        // issue next chunk's global loads early (hidden behind compute)
        if (more) {
            const float* An = Ab + (c + 1) * 32;
            const float* Bn = Bb + (c + 1) * 32;
            #pragma unroll
            for (int i = 0; i < 4; i++) {
                pa[i] = *(const float4*)(An + (size_t)rr[i] * K + cc[i]);
                pb[i] = *(const float4*)(Bn + (size_t)rr[i] * K + cc[i]);
            }
        }

        const uint32_t sbase = smem_base + stage * STAGE_BYTES;
        const uint32_t aH = sbase, aL = sbase + TSZ * 2;
        const uint32_t bH = sbase + 2 * TSZ * 2, bL = sbase + 3 * TSZ * 2;

        #pragma unroll
        for (int kt = 0; kt < 2; kt++) {
            uint32_t ah[4][4], al[4][4], bh[4][2], bl[4][2];
            #pragma unroll
            for (int mt = 0; mt < 4; mt++) {
                uint32_t off = ((uint32_t)(aRow + mt * 16) * PADW + aCol + kt * 16) * 2;
                ldmx4(ah[mt][0], ah[mt][1], ah[mt][2], ah[mt][3], aH + off);
                ldmx4(al[mt][0], al[mt][1], al[mt][2], al[mt][3], aL + off);
            }
            #pragma unroll
            for (int n2 = 0; n2 < 2; n2++) {
                uint32_t off = ((uint32_t)(bRow + n2 * 16) * PADW + bCol + kt * 16) * 2;
                uint32_t r0, r1, r2, r3;
                ldmx4(r0, r1, r2, r3, bH + off);
                bh[n2 * 2][0] = r0; bh[n2 * 2][1] = r1;
                bh[n2 * 2 + 1][0] = r2; bh[n2 * 2 + 1][1] = r3;
                ldmx4(r0, r1, r2, r3, bL + off);
                bl[n2 * 2][0] = r0; bl[n2 * 2][1] = r1;
                bl[n2 * 2 + 1][0] = r2; bl[n2 * 2 + 1][1] = r3;
            }
            #pragma unroll
            for (int mt = 0; mt < 4; mt++)
                #pragma unroll
                for (int nt = 0; nt < 4; nt++) {
                    mma16816(acc[mt][nt], ah[mt], bh[nt]);
                    mma16816(acc[mt][nt], ah[mt], bl[nt]);
                    mma16816(acc[mt][nt], al[mt], bh[nt]);
                }
        }

        if (more) {  // store next chunk into the other stage (prev compute on it
                     // finished before the last barrier)
            __nv_bfloat16* base = dsm + (stage ^ 1) * 4 * TSZ;
            __nv_bfloat16* sAh = base;
            __nv_bfloat16* sAl = base + TSZ;
            __nv_bfloat16* sBh = base + 2 * TSZ;
            __nv_bfloat16* sBl = base + 3 * TSZ;
            #pragma unroll
            for (int i = 0; i < 4; i++) {
                split_store4(pa[i], sAh + rr[i] * PADW + cc[i], sAl + rr[i] * PADW + cc[i]);
                split_store4(pb[i], sBh + rr[i] * PADW + cc[i], sBl + rr[i] * PADW + cc[i]);
            }
        }
        __syncthreads();
    }

    #pragma unroll
    for (int mt = 0; mt < 4; mt++) {
        int r0g = row0 + wm * 64 + mt * 16 + (lane >> 2);
        #pragma unroll
        for (int nt = 0; nt < 4; nt++) {
            int cg = col0 + wn * 32 + nt * 8 + (lane & 3) * 2;
            float2 v0 = make_float2(acc[mt][nt][0], acc[mt][nt][1]);
            float2 v1 = make_float2(acc[mt][nt][2], acc[mt][nt][3]);
            if (RES) {
                float2 q0 = *(const float2*)(Rsd + (size_t)r0g * N + cg);
                float2 q1 = *(const float2*)(Rsd + (size_t)(r0g + 8) * N + cg);
                v0.x += q0.x; v0.y += q0.y;
                v1.x += q1.x; v1.y += q1.y;
            }
            *(float2*)(C + (size_t)r0g * N + cg) = v0;
            *(float2*)(C + (size_t)(r0g + 8) * N + cg) = v1;
        }
    }
}

// ---------------- RMSNorm: one block per row ----------------
__global__ void rmsnorm_k(const float* __restrict__ x, const float* __restrict__ w,
                          float* __restrict__ out) {
    int row = blockIdx.x;
    const float* xr = x + row * HID;
    float ss = 0.f;
    for (int i = threadIdx.x; i < HID; i += 256) { float v = xr[i]; ss += v * v; }
    #pragma unroll
    for (int m = 16; m; m >>= 1) ss += __shfl_xor_sync(0xffffffffu, ss, m);
    __shared__ float red[8];
    if ((threadIdx.x & 31) == 0) red[threadIdx.x >> 5] = ss;
    __syncthreads();
    if (threadIdx.x < 8) {
        float r = red[threadIdx.x];
        #pragma unroll
        for (int m = 4; m; m >>= 1) r += __shfl_xor_sync(0xffu, r, m);
        if (threadIdx.x == 0) red[0] = r;
    }
    __syncthreads();
    float scale = rsqrtf(red[0] * (1.0f / (float)HID) + 1e-6f);
    for (int i = threadIdx.x; i < HID; i += 256)
        out[row * HID + i] = xr[i] * scale * w[i];
}

// ---------------- fused causal depthwise conv (K=4) + silu(silu(.)), 3 streams ----------------
struct CP3 { const float* in[3]; const float* w[3]; float* out[3]; };

__global__ void conv_silu2_k(CP3 p) {
    int z = blockIdx.y;
    const float* __restrict__ in = p.in[z];
    const float* __restrict__ w  = p.w[z];
    float* __restrict__ out = p.out[z];
    int idx = blockIdx.x * blockDim.x + threadIdx.x;
    int c = idx & (HID - 1);
    int t = idx >> 11;
    const float* wc = w + c * 4;
    float acc = 0.f;
    #pragma unroll
    for (int j = 0; j < 4; j++) {
        int ti = t - 3 + j;
        if (ti >= 0) acc = fmaf(in[ti * HID + c], wc[j], acc);
    }
    float s1 = acc / (1.f + expf(-acc));
    float s2 = s1 / (1.f + expf(-s1));
    out[idx] = s2;
}

// ---------------- per-head L2 norm (in-place), one warp per (t, head), 2 streams ----------------
__global__ void l2norm_k(float* __restrict__ pq, float* __restrict__ pk) {
    float* p = blockIdx.y ? pk : pq;
    int t = blockIdx.x;
    int h = threadIdx.x >> 5, l = threadIdx.x & 31;
    float* r = p + t * HID + h * HD;
    float a = r[l], b = r[l + 32];
    float ss = a * a + b * b;
    #pragma unroll
    for (int m = 16; m; m >>= 1) ss += __shfl_xor_sync(0xffffffffu, ss, m);
    float inv = 1.f / fmaxf(sqrtf(ss), 1e-12f);
    r[l] = a * inv;
    r[l + 32] = b * inv;
}

// ---------------- beta = sigmoid(h @ Wbeta^T), one warp per (t, head) ----------------
__global__ void beta_k(const float* __restrict__ hbuf, const float* __restrict__ Wb,
                       float* __restrict__ beta) {
    int t = blockIdx.x;
    int hh = threadIdx.x >> 5, l = threadIdx.x & 31;
    const float* hr = hbuf + t * HID;
    const float* wr = Wb + hh * HID;
    float s = 0.f;
    for (int i = l; i < HID; i += 32) s = fmaf(hr[i], wr[i], s);
    #pragma unroll
    for (int m = 16; m; m >>= 1) s += __shfl_xor_sync(0xffffffffu, s, m);
    if (l == 0) beta[t * NH + hh] = 1.f / (1.f + expf(-s));
}

// ---------------- delta scan ----------------
__global__ void delta_scan_k(const float* __restrict__ kb, const float* __restrict__ qb,
                             const float* __restrict__ vb, const float* __restrict__ betab,
                             float* __restrict__ ob, float* __restrict__ Sout) {
    int gtid = blockIdx.x * blockDim.x + threadIdx.x;
    int sub  = gtid & 3;
    int task = gtid >> 2;
    int head = task >> 6;
    int row  = task & 63;
    int c0   = sub << 4;

    float S[16];
    #pragma unroll
    for (int j = 0; j < 16; j++) S[j] = 0.f;

    const float* kp = kb + head * HD + c0;
    const float* qp = qb + head * HD + c0;
    const float* vp = vb + head * HD + row;
    const float* bp = betab + head;
    float* op = ob + head * HD + row;

    for (int t = 0; t < TT; t++) {
        float kk[16], qq[16];
        *(float4*)(kk)      = *(const float4*)(kp);
        *(float4*)(kk + 4)  = *(const float4*)(kp + 4);
        *(float4*)(kk + 8)  = *(const float4*)(kp + 8);
        *(float4*)(kk + 12) = *(const float4*)(kp + 12);
        *(float4*)(qq)      = *(const float4*)(qp);
        *(float4*)(qq + 4)  = *(const float4*)(qp + 4);
        *(float4*)(qq + 8)  = *(const float4*)(qp + 8);
        *(float4*)(qq + 12) = *(const float4*)(qp + 12);
        float vt = *vp;
        float bt = *bp;

        float a = 0.f, b = 0.f, c = 0.f;
        #pragma unroll
        for (int j = 0; j < 16; j++) {
            a = fmaf(S[j], kk[j], a);
            b = fmaf(S[j], qq[j], b);
            c = fmaf(kk[j], qq[j], c);
        }
        a += __shfl_xor_sync(0xffffffffu, a, 1);
        b += __shfl_xor_sync(0xffffffffu, b, 1);
        c += __shfl_xor_sync(0xffffffffu, c, 1);
        a += __shfl_xor_sync(0xffffffffu, a, 2);
        b += __shfl_xor_sync(0xffffffffu, b, 2);
        c += __shfl_xor_sync(0xffffffffu, c, 2);

        float coef = bt * (a - vt);
        float ot = b - coef * c;
        #pragma unroll
        for (int j = 0; j < 16; j++) S[j] = fmaf(-coef, kk[j], S[j]);
        if (sub == 0) op[t * HID] = ot;

        kp += HID; qp += HID; vp += HID; bp += NH;
    }

    #pragma unroll
    for (int j = 0; j < 16; j++)
        Sout[head * HD * HD + row * HD + c0 + j] = S[j];
}

// ---------------- SwiGLU elementwise ----------------
__global__ void swiglu_k(const float* __restrict__ g, const float* __restrict__ u,
                         float* __restrict__ out, int n) {
    int i = blockIdx.x * blockDim.x + threadIdx.x;
    if (i < n) {
        float x = g[i];
        out[i] = (x / (1.f + expf(-x))) * u[i];
    }
}

// ---------------- launch ----------------
extern "C" void kernel_launch(void* const* d_in, const int* in_sizes, int n_in,
                              void* d_out, int out_size) {
    const float* x_in   = (const float*)d_in[0];
    const float* attn_w = (const float*)d_in[1];
    const float* Wq     = (const float*)d_in[2];
    const float* Wk     = (const float*)d_in[3];
    const float* Wv     = (const float*)d_in[4];
    const float* cq     = (const float*)d_in[5];
    const float* ck     = (const float*)d_in[6];
    const float* cv     = (const float*)d_in[7];
    const float* Wb     = (const float*)d_in[8];
    const float* out_w  = (const float*)d_in[9];
    const float* Wout   = (const float*)d_in[10];
    const float* mlp_w  = (const float*)d_in[11];
    const float* Wg     = (const float*)d_in[12];
    const float* Wu     = (const float*)d_in[13];
    const float* Wd     = (const float*)d_in[14];

    float *h, *qr, *kr, *vr, *q, *k, *v, *beta, *o, *on, *x1, *h2, *gate, *up, *act, *Ssc;
    cudaGetSymbolAddress((void**)&h,   g_h);
    cudaGetSymbolAddress((void**)&qr,  g_qr);
    cudaGetSymbolAddress((void**)&kr,  g_kr);
    cudaGetSymbolAddress((void**)&vr,  g_vr);
    cudaGetSymbolAddress((void**)&q,   g_q);
    cudaGetSymbolAddress((void**)&k,   g_k);
    cudaGetSymbolAddress((void**)&v,   g_v);
    cudaGetSymbolAddress((void**)&beta,g_beta);
    cudaGetSymbolAddress((void**)&o,   g_o);
    cudaGetSymbolAddress((void**)&on,  g_on);
    cudaGetSymbolAddress((void**)&x1,  g_x1);
    cudaGetSymbolAddress((void**)&h2,  g_h2);
    cudaGetSymbolAddress((void**)&gate,g_gate);
    cudaGetSymbolAddress((void**)&up,  g_up);
    cudaGetSymbolAddress((void**)&act, g_act);
    cudaGetSymbolAddress((void**)&Ssc, g_Ssc);

    float* out_x = (float*)d_out;
    float* Sdst = (out_size >= TT * HID + NH * HD * HD) ? (out_x + TT * HID) : Ssc;

    const int DSMEM = 2 * STAGE_BYTES;  // 80 KB
    static int configured = 0;
    if (!configured) {
        cudaFuncSetAttribute(mgemm<0>, cudaFuncAttributeMaxDynamicSharedMemorySize, DSMEM);
        cudaFuncSetAttribute(mgemm<1>, cudaFuncAttributeMaxDynamicSharedMemorySize, DSMEM);
        configured = 1;
    }

    // ---- attention sub-block ----
    rmsnorm_k<<<TT, 256>>>(x_in, attn_w, h);

    {   // fused q/k/v projection
        P3 p = {{Wq, Wk, Wv}, {qr, kr, vr}, {nullptr, nullptr, nullptr}};
        dim3 g(HID / 128, TT / 128, 3);
        mgemm<0><<<g, 256, DSMEM>>>(h, p, TT, HID, HID);
    }

    {   // fused conv + double-silu for q/k/v
        CP3 cp = {{qr, kr, vr}, {cq, ck, cv}, {q, k, v}};
        dim3 g((TT * HID) / 256, 3);
        conv_silu2_k<<<g, 256>>>(cp);
    }

    l2norm_k<<<dim3(TT, 2), 1024>>>(q, k);
    beta_k<<<TT, 1024>>>(h, Wb, beta);

    delta_scan_k<<<64, 128>>>(k, q, v, beta, o, Sdst);

    rmsnorm_k<<<TT, 256>>>(o, out_w, on);
    {   // output projection + residual
        P3 p = {{Wout, nullptr, nullptr}, {x1, nullptr, nullptr}, {x_in, nullptr, nullptr}};
        dim3 g(HID / 128, TT / 128, 1);
        mgemm<1><<<g, 256, DSMEM>>>(on, p, TT, HID, HID);
    }

    // ---- MLP sub-block ----
    rmsnorm_k<<<TT, 256>>>(x1, mlp_w, h2);
    {   // fused gate + up projection
        P3 p = {{Wg, Wu, nullptr}, {gate, up, nullptr}, {nullptr, nullptr, nullptr}};
        dim3 g(INTER / 128, TT / 128, 2);
        mgemm<0><<<g, 256, DSMEM>>>(h2, p, TT, INTER, HID);
    }
    swiglu_k<<<(TT * INTER) / 256, 256>>>(gate, up, act, TT * INTER);
    {   // down projection + residual
        P3 p = {{Wd, nullptr, nullptr}, {out_x, nullptr, nullptr}, {x1, nullptr, nullptr}};
        dim3 g(HID / 128, TT / 128, 1);
        mgemm<1><<<g, 256, DSMEM>>>(act, p, TT, HID, INTER);
    }
}